// round 9
// baseline (speedup 1.0000x reference)
#include <cuda_runtime.h>
#include <cuda_fp16.h>
#include <math.h>
#include <stdint.h>

#define N_NODES 100000
#define N_EDGES 1600000
#define IN_F 64
#define HID_F 64
#define OUT_F 16

#define SCAN_B 1024
#define MAX_SCAN_BLKS 128

// ---- scratch (static __device__ globals) ----
__device__ __align__(16) int    g_cnt[N_NODES];     // in-degree (zeroed by last kernel)
__device__ __align__(16) int    g_row[N_NODES];     // CSR exclusive offsets (begin)
__device__ __align__(16) int    g_rank[N_EDGES];    // edge rank within dst bucket
__device__ __align__(16) int    g_blksum[MAX_SCAN_BLKS];
__device__ __align__(16) float  g_dis[N_NODES];     // rsqrt(deg+1); L2-resident 400KB
__device__ __align__(16) int    g_csr[N_EDGES];     // src only (dis looked up at gather)
__device__ __align__(16) __half g_h1[(size_t)N_NODES * HID_F];  // x@W1 (unscaled, fp16)
__device__ __align__(16) float  g_agg1[(size_t)N_NODES * HID_F];
__device__ __align__(16) __half g_h2[(size_t)N_NODES * OUT_F];  // layer-2 msgs (unscaled, fp16)

// inline dtype detect: int64 node ids < 2^31 have zero odd 32-bit words
__device__ __forceinline__ int edge_stride(const int* __restrict__ ei32, int E) {
    int is64 = 1;
    int n = E < 16 ? E : 16;
#pragma unroll
    for (int i = 0; i < 16; i++)
        if (i < n && ei32[2 * i + 1] != 0) is64 = 0;
    return is64 ? 2 : 1;
}

// ---------------------------------------------------------------------------
// GEMM1: h1 = x @ W1, fp16 out, unscaled. 128x64 block tile, 4x8 thread tile.
__global__ __launch_bounds__(256) void gemm1_kernel(
    const float* __restrict__ x, const float* __restrict__ W1, int N) {
    __shared__ float Wsh[IN_F][HID_F];   // 16KB
    __shared__ float Xsh[16][128];       // 8KB per k-chunk (transposed)

    int tid = threadIdx.x;
    int tx = tid & 7;
    int ty = tid >> 3;
    int nb = blockIdx.x * 128;

    for (int i = tid; i < 1024; i += 256) {
        int row = i >> 4, c4 = (i & 15) << 2;
        *reinterpret_cast<float4*>(&Wsh[row][c4]) =
            *reinterpret_cast<const float4*>(&W1[row * HID_F + c4]);
    }

    float acc[4][8];
#pragma unroll
    for (int i = 0; i < 4; i++)
#pragma unroll
        for (int j = 0; j < 8; j++) acc[i][j] = 0.0f;

    for (int kc = 0; kc < 4; kc++) {
        int k0 = kc * 16;
        __syncthreads();
        for (int i = tid; i < 512; i += 256) {
            int node = i >> 2, k4 = (i & 3) << 2;
            float4 v = make_float4(0.f, 0.f, 0.f, 0.f);
            int n = nb + node;
            if (n < N)
                v = *reinterpret_cast<const float4*>(&x[(size_t)n * IN_F + k0 + k4]);
            Xsh[k4 + 0][node] = v.x;
            Xsh[k4 + 1][node] = v.y;
            Xsh[k4 + 2][node] = v.z;
            Xsh[k4 + 3][node] = v.w;
        }
        __syncthreads();
#pragma unroll
        for (int k = 0; k < 16; k++) {
            float4 xv = *reinterpret_cast<const float4*>(&Xsh[k][ty * 4]);
            float4 wa = *reinterpret_cast<const float4*>(&Wsh[k0 + k][tx * 8]);
            float4 wb = *reinterpret_cast<const float4*>(&Wsh[k0 + k][tx * 8 + 4]);
            float xs[4] = {xv.x, xv.y, xv.z, xv.w};
#pragma unroll
            for (int i = 0; i < 4; i++) {
                acc[i][0] += xs[i] * wa.x;
                acc[i][1] += xs[i] * wa.y;
                acc[i][2] += xs[i] * wa.z;
                acc[i][3] += xs[i] * wa.w;
                acc[i][4] += xs[i] * wb.x;
                acc[i][5] += xs[i] * wb.y;
                acc[i][6] += xs[i] * wb.z;
                acc[i][7] += xs[i] * wb.w;
            }
        }
    }

#pragma unroll
    for (int i = 0; i < 4; i++) {
        int n = nb + ty * 4 + i;
        if (n >= N) continue;
        __align__(16) __half2 h[4];
#pragma unroll
        for (int p = 0; p < 4; p++)
            h[p] = __floats2half2_rn(acc[i][p * 2], acc[i][p * 2 + 1]);
        *reinterpret_cast<uint4*>(&g_h1[(size_t)n * HID_F + tx * 8]) =
            *reinterpret_cast<uint4*>(h);
    }
}

// degree histogram on dst; stores per-edge rank within its bucket
__global__ void build_hist_kernel(const int* __restrict__ ei32, int E) {
    int e = blockIdx.x * blockDim.x + threadIdx.x;
    if (e >= E) return;
    int stride = edge_stride(ei32, E);
    int dst = ei32[((size_t)E + e) * stride];
    g_rank[e] = atomicAdd(&g_cnt[dst], 1);
}

// per-block exclusive scan (warp-shuffle, 2 barriers)
__global__ __launch_bounds__(SCAN_B) void scan1_kernel(int N) {
    __shared__ int wsum[32];
    int i = blockIdx.x * SCAN_B + threadIdx.x;
    int v = (i < N) ? g_cnt[i] : 0;
    int lane = threadIdx.x & 31, wid = threadIdx.x >> 5;

    int s = v;
#pragma unroll
    for (int o = 1; o < 32; o *= 2) {
        int t = __shfl_up_sync(0xffffffffu, s, o);
        if (lane >= o) s += t;
    }
    if (lane == 31) wsum[wid] = s;
    __syncthreads();
    if (wid == 0) {
        int w = wsum[lane];
        int ws = w;
#pragma unroll
        for (int o = 1; o < 32; o *= 2) {
            int t = __shfl_up_sync(0xffffffffu, ws, o);
            if (lane >= o) ws += t;
        }
        wsum[lane] = ws - w;
        if (lane == 31) g_blksum[blockIdx.x] = ws;
    }
    __syncthreads();
    if (i < N) g_row[i] = wsum[wid] + s - v;       // exclusive
}

// fixup: warp 0 scans block sums (4/lane); final offsets + dis
__global__ void scan3_kernel(int N, int nblks) {
    __shared__ int excl[MAX_SCAN_BLKS];
    int lane = threadIdx.x & 31;
    if (threadIdx.x < 32) {
        int b4 = lane * 4;
        int v0 = (b4 + 0 < nblks) ? g_blksum[b4 + 0] : 0;
        int v1 = (b4 + 1 < nblks) ? g_blksum[b4 + 1] : 0;
        int v2 = (b4 + 2 < nblks) ? g_blksum[b4 + 2] : 0;
        int v3 = (b4 + 3 < nblks) ? g_blksum[b4 + 3] : 0;
        int s4 = v0 + v1 + v2 + v3;
        int ss = s4;
#pragma unroll
        for (int o = 1; o < 32; o *= 2) {
            int t = __shfl_up_sync(0xffffffffu, ss, o);
            if (lane >= o) ss += t;
        }
        int ex = ss - s4;
        excl[b4 + 0] = ex;
        excl[b4 + 1] = ex + v0;
        excl[b4 + 2] = ex + v0 + v1;
        excl[b4 + 3] = ex + v0 + v1 + v2;
    }
    __syncthreads();
    int i = blockIdx.x * blockDim.x + threadIdx.x;
    if (i >= N) return;
    g_row[i] += excl[i >> 10];
    g_dis[i] = rsqrtf((float)(g_cnt[i] + 1));
}

// bucket fill — atomic-free, src-only entry: pos = row[dst] + rank[e]
__global__ void fill_kernel(const int* __restrict__ ei32, int E) {
    int e = blockIdx.x * blockDim.x + threadIdx.x;
    if (e >= E) return;
    int stride = edge_stride(ei32, E);
    int src = ei32[(size_t)e * stride];
    int dst = ei32[((size_t)E + e) * stride];
    int pos = g_row[dst] + g_rank[e];
    g_csr[pos] = src;
}

// ---------------------------------------------------------------------------
// gather layer 1: agg1[n] = dis[n] * ( dis[n]*h1[n] + sum_s dis[s]*h1[s] )
// 8 threads/node, 8 halves each; 2-edge unroll; dis[s] from L2-hot table.
__global__ __launch_bounds__(256) void gather1_kernel(int N) {
    int t = blockIdx.x * blockDim.x + threadIdx.x;
    int n = t >> 3;
    int c = t & 7;
    if (n >= N) return;

    unsigned lane = threadIdx.x & 31;
    unsigned gmask = 0xffu << (lane & ~7u);

    float dn = g_dis[n];
    int beg = g_row[n];
    int end = beg + g_cnt[n];

    float acc[8];
    {   // self term: dis[n] * h1[n]
        uint4 raw = *reinterpret_cast<const uint4*>(&g_h1[(size_t)n * HID_F + c * 8]);
        const __half2* hp = reinterpret_cast<const __half2*>(&raw);
#pragma unroll
        for (int p = 0; p < 4; p++) {
            float2 f = __half22float2(hp[p]);
            acc[p * 2 + 0] = dn * f.x;
            acc[p * 2 + 1] = dn * f.y;
        }
    }

    int j = beg;
    for (; j + 2 <= end; j += 2) {
        int sld = 0; float dld = 0.f;
        if (c < 2) { sld = g_csr[j + c]; dld = g_dis[sld]; }
        int   s0 = __shfl_sync(gmask, sld, 0, 8);
        float d0 = __shfl_sync(gmask, dld, 0, 8);
        int   s1 = __shfl_sync(gmask, sld, 1, 8);
        float d1 = __shfl_sync(gmask, dld, 1, 8);

        uint4 ra = *reinterpret_cast<const uint4*>(&g_h1[(size_t)s0 * HID_F + c * 8]);
        uint4 rb = *reinterpret_cast<const uint4*>(&g_h1[(size_t)s1 * HID_F + c * 8]);
        const __half2* ha = reinterpret_cast<const __half2*>(&ra);
        const __half2* hb = reinterpret_cast<const __half2*>(&rb);
#pragma unroll
        for (int p = 0; p < 4; p++) {
            float2 fa = __half22float2(ha[p]);
            float2 fb = __half22float2(hb[p]);
            acc[p * 2 + 0] += d0 * fa.x + d1 * fb.x;
            acc[p * 2 + 1] += d0 * fa.y + d1 * fb.y;
        }
    }
    if (j < end) {
        int sld = 0; float dld = 0.f;
        if (c == 0) { sld = g_csr[j]; dld = g_dis[sld]; }
        int   s0 = __shfl_sync(gmask, sld, 0, 8);
        float d0 = __shfl_sync(gmask, dld, 0, 8);
        uint4 ra = *reinterpret_cast<const uint4*>(&g_h1[(size_t)s0 * HID_F + c * 8]);
        const __half2* ha = reinterpret_cast<const __half2*>(&ra);
#pragma unroll
        for (int p = 0; p < 4; p++) {
            float2 fa = __half22float2(ha[p]);
            acc[p * 2 + 0] += d0 * fa.x;
            acc[p * 2 + 1] += d0 * fa.y;
        }
    }

    float4 o0 = make_float4(acc[0] * dn, acc[1] * dn, acc[2] * dn, acc[3] * dn);
    float4 o1 = make_float4(acc[4] * dn, acc[5] * dn, acc[6] * dn, acc[7] * dn);
    float* dst = &g_agg1[(size_t)n * HID_F + c * 8];
    *reinterpret_cast<float4*>(dst) = o0;
    *reinterpret_cast<float4*>(dst + 4) = o1;
}

// GEMM2: h2 = relu(agg1 + b1) @ W2, fp16 out, unscaled. 2 nodes/thread.
__global__ __launch_bounds__(256) void gemm2_kernel(
    const float* __restrict__ W2, const float* __restrict__ b1, int N) {
    __shared__ float Wsh[HID_F][OUT_F];
    __shared__ float bsh[HID_F];
    for (int i = threadIdx.x; i < HID_F * OUT_F; i += blockDim.x)
        Wsh[i >> 4][i & 15] = W2[i];
    if (threadIdx.x < HID_F) bsh[threadIdx.x] = b1[threadIdx.x];
    __syncthreads();

    int t = blockIdx.x * blockDim.x + threadIdx.x;
    int n0 = t * 2, n1 = t * 2 + 1;
    if (n0 >= N) return;
    bool has1 = (n1 < N);

    float acc0[OUT_F], acc1[OUT_F];
#pragma unroll
    for (int j = 0; j < OUT_F; j++) { acc0[j] = 0.0f; acc1[j] = 0.0f; }

    const float4* a0 = reinterpret_cast<const float4*>(&g_agg1[(size_t)n0 * HID_F]);
    const float4* a1 = reinterpret_cast<const float4*>(&g_agg1[(size_t)n1 * HID_F]);

#pragma unroll 4
    for (int k4 = 0; k4 < HID_F / 4; k4++) {
        float4 v0 = a0[k4];
        float4 v1 = has1 ? a1[k4] : make_float4(0.f, 0.f, 0.f, 0.f);
        float h0s[4] = {v0.x, v0.y, v0.z, v0.w};
        float h1s[4] = {v1.x, v1.y, v1.z, v1.w};
#pragma unroll
        for (int kk = 0; kk < 4; kk++) {
            int k = k4 * 4 + kk;
            float bb = bsh[k];
            float h0 = fmaxf(h0s[kk] + bb, 0.0f);
            float h1 = fmaxf(h1s[kk] + bb, 0.0f);
#pragma unroll
            for (int j4 = 0; j4 < OUT_F / 4; j4++) {
                float4 w = *reinterpret_cast<const float4*>(&Wsh[k][j4 * 4]);
                acc0[j4 * 4 + 0] += h0 * w.x;  acc1[j4 * 4 + 0] += h1 * w.x;
                acc0[j4 * 4 + 1] += h0 * w.y;  acc1[j4 * 4 + 1] += h1 * w.y;
                acc0[j4 * 4 + 2] += h0 * w.z;  acc1[j4 * 4 + 2] += h1 * w.z;
                acc0[j4 * 4 + 3] += h0 * w.w;  acc1[j4 * 4 + 3] += h1 * w.w;
            }
        }
    }

    {
        __align__(16) __half2 h[8];
#pragma unroll
        for (int p = 0; p < 8; p++)
            h[p] = __floats2half2_rn(acc0[p * 2], acc0[p * 2 + 1]);
        *reinterpret_cast<uint4*>(&g_h2[(size_t)n0 * OUT_F]) =
            *reinterpret_cast<uint4*>(&h[0]);
        *reinterpret_cast<uint4*>(&g_h2[(size_t)n0 * OUT_F + 8]) =
            *reinterpret_cast<uint4*>(&h[4]);
    }
    if (has1) {
        __align__(16) __half2 h[8];
#pragma unroll
        for (int p = 0; p < 8; p++)
            h[p] = __floats2half2_rn(acc1[p * 2], acc1[p * 2 + 1]);
        *reinterpret_cast<uint4*>(&g_h2[(size_t)n1 * OUT_F]) =
            *reinterpret_cast<uint4*>(&h[0]);
        *reinterpret_cast<uint4*>(&g_h2[(size_t)n1 * OUT_F + 8]) =
            *reinterpret_cast<uint4*>(&h[4]);
    }
}

// gather layer 2 + log_softmax fused. 4 threads/node, 4 feats (8B fp16) each.
__global__ __launch_bounds__(256) void gather2_lsm_kernel(
    const float* __restrict__ b2, float* __restrict__ out, int N) {
    int t = blockIdx.x * blockDim.x + threadIdx.x;
    int n = t >> 2;
    int c = t & 3;
    if (n >= N) return;

    unsigned lane = threadIdx.x & 31;
    unsigned gmask = 0xfu << (lane & ~3u);

    float dn = g_dis[n];
    int beg = g_row[n];
    int end = beg + g_cnt[n];

    float acc[4];
    {
        uint2 raw = *reinterpret_cast<const uint2*>(&g_h2[(size_t)n * OUT_F + c * 4]);
        const __half2* hp = reinterpret_cast<const __half2*>(&raw);
        float2 f0 = __half22float2(hp[0]);
        float2 f1 = __half22float2(hp[1]);
        acc[0] = dn * f0.x; acc[1] = dn * f0.y;
        acc[2] = dn * f1.x; acc[3] = dn * f1.y;
    }

    int j = beg;
    for (; j + 2 <= end; j += 2) {
        int sld = 0; float dld = 0.f;
        if (c < 2) { sld = g_csr[j + c]; dld = g_dis[sld]; }
        int   s0 = __shfl_sync(gmask, sld, 0, 4);
        float d0 = __shfl_sync(gmask, dld, 0, 4);
        int   s1 = __shfl_sync(gmask, sld, 1, 4);
        float d1 = __shfl_sync(gmask, dld, 1, 4);
        uint2 ra = *reinterpret_cast<const uint2*>(&g_h2[(size_t)s0 * OUT_F + c * 4]);
        uint2 rb = *reinterpret_cast<const uint2*>(&g_h2[(size_t)s1 * OUT_F + c * 4]);
        const __half2* ha = reinterpret_cast<const __half2*>(&ra);
        const __half2* hb = reinterpret_cast<const __half2*>(&rb);
        float2 a0 = __half22float2(ha[0]), a1 = __half22float2(ha[1]);
        float2 b0 = __half22float2(hb[0]), b1f = __half22float2(hb[1]);
        acc[0] += d0 * a0.x + d1 * b0.x;
        acc[1] += d0 * a0.y + d1 * b0.y;
        acc[2] += d0 * a1.x + d1 * b1f.x;
        acc[3] += d0 * a1.y + d1 * b1f.y;
    }
    if (j < end) {
        int sld = 0; float dld = 0.f;
        if (c == 0) { sld = g_csr[j]; dld = g_dis[sld]; }
        int   s0 = __shfl_sync(gmask, sld, 0, 4);
        float d0 = __shfl_sync(gmask, dld, 0, 4);
        uint2 ra = *reinterpret_cast<const uint2*>(&g_h2[(size_t)s0 * OUT_F + c * 4]);
        const __half2* ha = reinterpret_cast<const __half2*>(&ra);
        float2 a0 = __half22float2(ha[0]), a1 = __half22float2(ha[1]);
        acc[0] += d0 * a0.x;
        acc[1] += d0 * a0.y;
        acc[2] += d0 * a1.x;
        acc[3] += d0 * a1.y;
    }

    float4 bb = *reinterpret_cast<const float4*>(&b2[c * 4]);
    float v[4] = {acc[0] * dn + bb.x, acc[1] * dn + bb.y,
                  acc[2] * dn + bb.z, acc[3] * dn + bb.w};

    float mx = fmaxf(fmaxf(v[0], v[1]), fmaxf(v[2], v[3]));
    mx = fmaxf(mx, __shfl_xor_sync(gmask, mx, 1, 4));
    mx = fmaxf(mx, __shfl_xor_sync(gmask, mx, 2, 4));
    float s = __expf(v[0] - mx) + __expf(v[1] - mx) +
              __expf(v[2] - mx) + __expf(v[3] - mx);
    s += __shfl_xor_sync(gmask, s, 1, 4);
    s += __shfl_xor_sync(gmask, s, 2, 4);
    float ls = mx + logf(s);

    *reinterpret_cast<float4*>(&out[(size_t)n * OUT_F + c * 4]) =
        make_float4(v[0] - ls, v[1] - ls, v[2] - ls, v[3] - ls);

    if (c == 0) g_cnt[n] = 0;
}

// ---------------------------------------------------------------------------
extern "C" void kernel_launch(void* const* d_in, const int* in_sizes, int n_in,
                              void* d_out, int out_size) {
    const float* x    = (const float*)d_in[0];
    const int*   ei32 = (const int*)d_in[1];
    const float* W1   = (const float*)d_in[2];
    const float* b1   = (const float*)d_in[3];
    const float* W2   = (const float*)d_in[4];
    const float* b2   = (const float*)d_in[5];
    float* out = (float*)d_out;

    int N = in_sizes[0] / IN_F;
    int E = in_sizes[1] / 2;

    const int T = 256;
    int gE = (E + T - 1) / T;
    int gN = (N + T - 1) / T;
    int nScanBlks = (N + SCAN_B - 1) / SCAN_B;

    static cudaStream_t s_side = 0;
    static cudaEvent_t ev_fork = 0, ev_join = 0;
    static int s_init = 0;
    if (!s_init) {
        s_init = 1;
        if (cudaStreamCreateWithFlags(&s_side, cudaStreamNonBlocking) != cudaSuccess)
            s_side = 0;
        if (s_side) {
            if (cudaEventCreateWithFlags(&ev_fork, cudaEventDisableTiming) != cudaSuccess ||
                cudaEventCreateWithFlags(&ev_join, cudaEventDisableTiming) != cudaSuccess)
                s_side = 0;
        }
    }

    if (s_side) {
        cudaEventRecord(ev_fork, 0);
        cudaStreamWaitEvent(s_side, ev_fork, 0);

        build_hist_kernel<<<gE, T, 0, s_side>>>(ei32, E);     // 1
        scan1_kernel<<<nScanBlks, SCAN_B, 0, s_side>>>(N);    // 2
        scan3_kernel<<<gN, T, 0, s_side>>>(N, nScanBlks);     // 3
        fill_kernel<<<gE, T, 0, s_side>>>(ei32, E);           // 4 <- profiled
        gemm1_kernel<<<(N + 127) / 128, 256>>>(x, W1, N);     // 5 (main, concurrent)

        cudaEventRecord(ev_join, s_side);
        cudaStreamWaitEvent(0, ev_join, 0);
    } else {
        gemm1_kernel<<<(N + 127) / 128, 256>>>(x, W1, N);
        build_hist_kernel<<<gE, T>>>(ei32, E);
        scan1_kernel<<<nScanBlks, SCAN_B>>>(N);
        scan3_kernel<<<gN, T>>>(N, nScanBlks);
        fill_kernel<<<gE, T>>>(ei32, E);
    }

    gather1_kernel<<<(N * 8 + T - 1) / T, T>>>(N);                 // 6
    gemm2_kernel<<<((N + 1) / 2 + T - 1) / T, T>>>(W2, b1, N);     // 7
    gather2_lsm_kernel<<<(N * 4 + T - 1) / T, T>>>(b2, out, N);    // 8
}